// round 8
// baseline (speedup 1.0000x reference)
#include <cuda_runtime.h>

// Problem constants
#define N 256
#define H 1024
#define M 256
#define ZLEN (M + N)   // 512
#define NT 512         // threads per block
#define NW (NT / 32)   // 16 warps

__device__ __forceinline__ float warp_reduce(float v) {
    #pragma unroll
    for (int o = 16; o > 0; o >>= 1)
        v += __shfl_xor_sync(0xffffffffu, v, o);
    return v;
}

// reduce across the 8 lanes sharing one row (s = lane&7)
__device__ __forceinline__ float octet_reduce(float v) {
    v += __shfl_xor_sync(0xffffffffu, v, 4);
    v += __shfl_xor_sync(0xffffffffu, v, 2);
    v += __shfl_xor_sync(0xffffffffu, v, 1);
    return v;
}

__device__ __forceinline__ float dot4(float4 a, float4 b) {
    return a.x * b.x + a.y * b.y + a.z * b.z + a.w * b.w;
}

// One block per node n. Whole pipeline fused; intermediates in smem.
// Phases 1 & 3: each warp handles 4 rows at once (8 lanes per row) —
// same 128B-coalesced loads, but reduce depth 3 instead of 5 and
// 4 independent accumulator chains per warp.
__global__ __launch_bounds__(NT, 2) void fused_all(
    const float* __restrict__ x,
    const float* __restrict__ W1, const float* __restrict__ W2,
    const float* __restrict__ W3, const float* __restrict__ b3,
    const float* __restrict__ W4, const float* __restrict__ b4,
    float* __restrict__ out)
{
    const int n    = blockIdx.x;
    const int tid  = threadIdx.x;
    const int wid  = tid >> 5;
    const int lane = tid & 31;
    const int r    = lane >> 3;   // row within 4-row group
    const int s    = lane & 7;    // lane within row

    __shared__ float4 xs4[N / 4];   // masked x   (1 KB)
    __shared__ float4 r1s[H / 4];   // r1         (4 KB)
    __shared__ float4 r2s[M / 4];   // r2         (1 KB)
    __shared__ float  wsum[NW];

    // Load masked x: element n zeroed
    if (tid < N / 4) {
        float4 v = reinterpret_cast<const float4*>(x)[tid];
        const int base = tid * 4;
        if (n == base + 0) v.x = 0.f;
        if (n == base + 1) v.y = 0.f;
        if (n == base + 2) v.z = 0.f;
        if (n == base + 3) v.w = 0.f;
        xs4[tid] = v;
    }
    __syncthreads();

    // ---- Phase 1: r1 = relu(W1[n] @ xmask), 4 rows per warp-group ----
    {
        const float4* W1b = reinterpret_cast<const float4*>(
            W1 + (size_t)n * H * N);
        float* r1f = reinterpret_cast<float*>(r1s);
        #pragma unroll 2
        for (int g = 0; g < H / (NW * 4); g++) {     // 16 groups per warp
            const int hbase = (g * NW + wid) * 4;
            const float4* row = W1b + (size_t)(hbase + r) * (N / 4) + s;
            float acc = 0.f;
            #pragma unroll
            for (int k = 0; k < 8; k++)              // 8 passes over 64 float4
                acc += dot4(__ldcs(row + k * 8), xs4[k * 8 + s]);
            acc = octet_reduce(acc);
            if (s == 0) r1f[hbase + r] = fmaxf(acc, 0.f);
        }
    }
    __syncthreads();

    // ---- Phase 2: r2 = relu(W2[n] @ r1) (unchanged from champion) ----
    {
        const float4* W2b = reinterpret_cast<const float4*>(
            W2 + (size_t)n * M * H);
        float* r2f = reinterpret_cast<float*>(r2s);
        #pragma unroll 2
        for (int i = 0; i < M / NW; i++) {          // 16 rows per warp
            const int m = wid + i * NW;
            const float4* row = W2b + (size_t)m * (H / 4);
            float acc = 0.f;
            #pragma unroll
            for (int k = 0; k < H / 4 / 32; k++)    // 8 float4 per lane
                acc += dot4(__ldcs(row + lane + k * 32), r1s[lane + k * 32]);
            acc = warp_reduce(acc);
            if (lane == 0) r2f[m] = fmaxf(acc, 0.f);
        }
    }
    __syncthreads();

    // ---- Phase 3: h = relu(W3[:,0:M].r2 + oh*x[n] + b3); fold W4 ----
    {
        const float* W3b = W3 + (size_t)n * H * ZLEN;
        const float* b3b = b3 + (size_t)n * H;
        const float* W4b = W4 + (size_t)n * H;
        const float  xn  = x[n];

        float wacc = 0.f;   // accumulated on s==0 lanes (4 per warp)
        #pragma unroll 2
        for (int g = 0; g < H / (NW * 4); g++) {     // 16 groups per warp
            const int hbase = (g * NW + wid) * 4;
            const int hh = hbase + r;
            const float* rowf = W3b + (size_t)hh * ZLEN;
            const float4* row = reinterpret_cast<const float4*>(rowf) + s;
            float acc = 0.f;
            #pragma unroll
            for (int k = 0; k < 8; k++)              // first M cols (64 float4)
                acc += dot4(__ldcs(row + k * 8), r2s[k * 8 + s]);
            acc = octet_reduce(acc);
            if (s == 0) {
                float hv = fmaxf(acc + rowf[M + n] * xn + b3b[hh], 0.f);
                wacc += hv * W4b[hh];
            }
        }
        // sum the 4 leader lanes (others contribute 0)
        wacc = warp_reduce(wacc);
        if (lane == 0) wsum[wid] = wacc;
    }
    __syncthreads();

    if (tid == 0) {
        float ssum = 0.f;
        #pragma unroll
        for (int i = 0; i < NW; i++) ssum += wsum[i];
        out[n] = fmaxf(ssum + b4[n], 0.f);
    }
}

extern "C" void kernel_launch(void* const* d_in, const int* in_sizes, int n_in,
                              void* d_out, int out_size)
{
    // Input order (metadata): x, W1, W2, W3, b3, W4, b4, t
    const float* x  = (const float*)d_in[0];
    const float* W1 = (const float*)d_in[1];
    const float* W2 = (const float*)d_in[2];
    const float* W3 = (const float*)d_in[3];
    const float* b3 = (const float*)d_in[4];
    const float* W4 = (const float*)d_in[5];
    const float* b4 = (const float*)d_in[6];
    float* out = (float*)d_out;

    fused_all<<<N, NT>>>(x, W1, W2, W3, b3, W4, b4, out);
}

// round 9
// speedup vs baseline: 1.0322x; 1.0322x over previous
#include <cuda_runtime.h>

// Problem constants
#define N 256
#define H 1024
#define M 256
#define ZLEN (M + N)   // 512
#define NT 512         // threads per block
#define NW (NT / 32)   // 16 warps

__device__ __forceinline__ float warp_reduce(float v) {
    #pragma unroll
    for (int o = 16; o > 0; o >>= 1)
        v += __shfl_xor_sync(0xffffffffu, v, o);
    return v;
}

__device__ __forceinline__ float dot4(float4 a, float4 b) {
    return a.x * b.x + a.y * b.y + a.z * b.z + a.w * b.w;
}

// One block per node n. Whole pipeline in one kernel; intermediates in smem.
//   phase1: r1[h] = relu(W1[n,h,:] . xmask)            (H outputs)
//   phase2: r2[m] = relu(W2[n,m,:] . r1)               (M outputs)
//   phase3: h[hh] = relu(W3[n,hh,0:M].r2 + W3[n,hh,M+n]*x[n] + b3[n,hh])
//           acc  += W4[n,hh] * h[hh]                   (folded, no h buffer)
//   out[n] = relu(acc + b4[n])
__global__ __launch_bounds__(NT, 2) void fused_all(
    const float* __restrict__ x,
    const float* __restrict__ W1, const float* __restrict__ W2,
    const float* __restrict__ W3, const float* __restrict__ b3,
    const float* __restrict__ W4, const float* __restrict__ b4,
    float* __restrict__ out)
{
    const int n    = blockIdx.x;
    const int tid  = threadIdx.x;
    const int wid  = tid >> 5;
    const int lane = tid & 31;

    __shared__ float4 xs4[N / 4];   // masked x   (1 KB)
    __shared__ float4 r1s[H / 4];   // r1         (4 KB)
    __shared__ float4 r2s[M / 4];   // r2         (1 KB)
    __shared__ float  wsum[NW];

    // Load masked x: element n zeroed
    if (tid < N / 4) {
        float4 v = reinterpret_cast<const float4*>(x)[tid];
        const int base = tid * 4;
        if (n == base + 0) v.x = 0.f;
        if (n == base + 1) v.y = 0.f;
        if (n == base + 2) v.z = 0.f;
        if (n == base + 3) v.w = 0.f;
        xs4[tid] = v;
    }
    __syncthreads();

    // ---- Phase 1: r1 = relu(W1[n] @ xmask), warp-per-row, strided rows ----
    {
        const float4* W1b = reinterpret_cast<const float4*>(
            W1 + (size_t)n * H * N);
        float* r1f = reinterpret_cast<float*>(r1s);
        #pragma unroll 16
        for (int i = 0; i < H / NW; i++) {      // 64 rows per warp
            const int h = wid + i * NW;
            const float4* row = W1b + (size_t)h * (N / 4);
            float acc = dot4(__ldcs(row + lane),      xs4[lane])
                      + dot4(__ldcs(row + lane + 32), xs4[lane + 32]);
            acc = warp_reduce(acc);
            if (lane == 0) r1f[h] = fmaxf(acc, 0.f);
        }
    }
    __syncthreads();

    // ---- Phase 2: r2 = relu(W2[n] @ r1) ----
    {
        const float4* W2b = reinterpret_cast<const float4*>(
            W2 + (size_t)n * M * H);
        float* r2f = reinterpret_cast<float*>(r2s);
        #pragma unroll 2
        for (int i = 0; i < M / NW; i++) {      // 16 rows per warp
            const int m = wid + i * NW;
            const float4* row = W2b + (size_t)m * (H / 4);
            float acc = 0.f;
            #pragma unroll
            for (int k = 0; k < H / 4 / 32; k++)    // 8 float4 per lane
                acc += dot4(__ldcs(row + lane + k * 32), r1s[lane + k * 32]);
            acc = warp_reduce(acc);
            if (lane == 0) r2f[m] = fmaxf(acc, 0.f);
        }
    }
    __syncthreads();

    // ---- Phase 3: h = relu(W3[:,0:M].r2 + onehot + b3); fold W4 ----
    {
        const float* W3b = W3 + (size_t)n * H * ZLEN;
        const float* b3b = b3 + (size_t)n * H;
        const float* W4b = W4 + (size_t)n * H;
        const float  xn  = x[n];

        float wacc = 0.f;   // meaningful on lane 0 only
        #pragma unroll 8
        for (int i = 0; i < H / NW; i++) {      // 64 rows per warp
            const int hh = wid + i * NW;
            const float* rowf = W3b + (size_t)hh * ZLEN;
            const float4* row = reinterpret_cast<const float4*>(rowf);
            float acc = dot4(__ldcs(row + lane),      r2s[lane])
                      + dot4(__ldcs(row + lane + 32), r2s[lane + 32]);
            acc = warp_reduce(acc);
            if (lane == 0) {
                float hv = fmaxf(acc + rowf[M + n] * xn + b3b[hh], 0.f);
                wacc += hv * W4b[hh];
            }
        }
        if (lane == 0) wsum[wid] = wacc;
    }
    __syncthreads();

    if (tid == 0) {
        float s = 0.f;
        #pragma unroll
        for (int i = 0; i < NW; i++) s += wsum[i];
        out[n] = fmaxf(s + b4[n], 0.f);
    }
}

extern "C" void kernel_launch(void* const* d_in, const int* in_sizes, int n_in,
                              void* d_out, int out_size)
{
    // Input order (metadata): x, W1, W2, W3, b3, W4, b4, t
    const float* x  = (const float*)d_in[0];
    const float* W1 = (const float*)d_in[1];
    const float* W2 = (const float*)d_in[2];
    const float* W3 = (const float*)d_in[3];
    const float* b3 = (const float*)d_in[4];
    const float* W4 = (const float*)d_in[5];
    const float* b4 = (const float*)d_in[6];
    float* out = (float*)d_out;

    fused_all<<<N, NT>>>(x, W1, W2, W3, b3, W4, b4, out);
}